// round 2
// baseline (speedup 1.0000x reference)
#include <cuda_runtime.h>

// ---------------------------------------------------------------------------
// DLinear_436 collapsed to a per-pixel linear map with (hc,wc) position-class
// weights; trend (moving-avg, window 25 >= 2*T) is affine in t and folded into
// D0/D1 tables.  Main kernel: blocks grouped by hc, full 64-wide rows =>
// coalesced gmem; 12 wc-class tables in 132KB dynamic smem with bank-quad-
// disjoint class stride; packed fma.rn.f32x2 inner product.
// ---------------------------------------------------------------------------

#define NB    32
#define T_IN  12
#define HH    64
#define WW    64
#define C_IN  4
#define NO    48
#define TC    48
#define NCLS  144
#define HW    4096

#define SW_STRIDE 2308          // floats per class for W table (mod 8 == 4)
#define SD_STRIDE 196           // floats per class for D0/D1   (mod 8 == 4)
#define SB_STRIDE 49            // floats per class for bias
#define OFF_D0 (12 * SW_STRIDE)             // 27696
#define OFF_D1 (OFF_D0 + 12 * SD_STRIDE)    // 30048
#define OFF_B  (OFF_D1 + 12 * SD_STRIDE)    // 32400
#define SMEM_FLOATS (OFF_B + 12 * SB_STRIDE)  // 32988
#define SMEM_BYTES  (SMEM_FLOATS * 4)         // 131952

// Per-class folded weight tables (prep kernel output), compact layout.
__device__ float gW [NCLS][NO][TC];
__device__ float gD0[NCLS][NO][4];
__device__ float gD1[NCLS][NO][4];
__device__ float gB [NCLS][NO];

#define FMA2(d,a,b,c) asm("fma.rn.f32x2 %0, %1, %2, %3;" : "=l"(d) : "l"(a), "l"(b), "l"(c))
#define ADD2(d,a,b)   asm("add.rn.f32x2 %0, %1, %2;"     : "=l"(d) : "l"(a), "l"(b))
#define MUL2(d,a,b)   asm("mul.rn.f32x2 %0, %1, %2;"     : "=l"(d) : "l"(a), "l"(b))
#define UNPACK2(lo,hi,v) asm("mov.b64 {%0, %1}, %2;" : "=f"(lo), "=f"(hi) : "l"(v))

__device__ __forceinline__ int class_ilist(int hc, int idx[2]) {
    if (hc < 4)  { idx[0] = hc;                      return 1; }
    if (hc < 8)  { idx[0] = hc - 4; idx[1] = hc;     return 2; }
    idx[0] = hc - 4;                                 return 1;
}

// ---------------------------------------------------------------------------
// Prep: fold raw weights into per-class tables.  Trivial cost.
// ---------------------------------------------------------------------------
__global__ void dlinear_prep_kernel(const float* __restrict__ w_s,
                                    const float* __restrict__ b_s,
                                    const float* __restrict__ w_t,
                                    const float* __restrict__ b_t) {
    int cls = blockIdx.x;
    int hc = cls / 12, wc = cls % 12;
    int il[2], jl[2];
    int ni = class_ilist(hc, il);
    int nj = class_ilist(wc, jl);

    for (int idx = threadIdx.x; idx < NO * TC; idx += blockDim.x) {
        int o = idx / TC, tc = idx % TC;
        const float* wp = w_s + (o * TC + tc) * 64;
        float s = 0.f;
        for (int a = 0; a < ni; a++)
            for (int e = 0; e < nj; e++)
                s += wp[il[a] * 8 + jl[e]];
        gW[cls][o][tc] = s;
    }

    for (int idx = threadIdx.x; idx < NO * 4; idx += blockDim.x) {
        int o = idx / 4, c = idx % 4;
        float d0 = 0.f, d1 = 0.f;
        for (int t = 0; t < T_IN; t++) {
            const float* ps = w_s + ((o * T_IN + t) * 4 + c) * 64;
            const float* pt = w_t + ((o * T_IN + t) * 4 + c) * 64;
            float d = 0.f;
            for (int a = 0; a < ni; a++)
                for (int e = 0; e < nj; e++) {
                    int off = il[a] * 8 + jl[e];
                    d += pt[off] - ps[off];
                }
            d0 += d;
            d1 += (float)t * d;
        }
        gD0[cls][o][c] = d0;
        gD1[cls][o][c] = d1;
    }

    for (int o = threadIdx.x; o < NO; o += blockDim.x) {
        float s = 0.f;
        for (int a = 0; a < ni; a++)
            for (int e = 0; e < nj; e++) {
                int off = o * 64 + il[a] * 8 + jl[e];
                s += b_s[off] + b_t[off];
            }
        gB[cls][o] = s;
    }
}

// ---------------------------------------------------------------------------
// Main.  Static schedule: 256 blocks x 512 threads, 1 iteration each.
//   bid <  224: interior hc = 4 + bid/56,  rows (bid%56)*8 .. +7   (448 rows/hc)
//   bid >= 224: edge: e=bid-224, hc = e/4 (<4) or e/4+4, rows (e%4)*8..+7 (32)
// Thread -> (row r0 + tid/64, w = tid&63).  Lanes contiguous in w.
// ---------------------------------------------------------------------------
__global__ __launch_bounds__(512, 1)
void dlinear_main_kernel(const float* __restrict__ x, float* __restrict__ out) {
    extern __shared__ float sm[];
    const int tid = threadIdx.x;
    const int bid = blockIdx.x;

    int hc, r0;
    if (bid < 224) {
        hc = 4 + bid / 56;
        r0 = (bid % 56) * 8;
    } else {
        int e = bid - 224;
        int g = e >> 2;
        hc = (g < 4) ? g : g + 4;
        r0 = (e & 3) * 8;
    }

    // ---- fill smem (12 wc classes of this hc; compact source is contiguous)
    {
        const float4* srcW = (const float4*)&gW[hc * 12][0][0];
        for (int i = tid; i < 12 * 576; i += 512) {
            int c = i / 576, q = i - c * 576;
            ((float4*)(sm + c * SW_STRIDE))[q] = srcW[i];
        }
        const float4* s0 = (const float4*)&gD0[hc * 12][0][0];
        const float4* s1 = (const float4*)&gD1[hc * 12][0][0];
        for (int i = tid; i < 12 * 48; i += 512) {
            int c = i / 48, o = i - c * 48;
            ((float4*)(sm + OFF_D0 + c * SD_STRIDE))[o] = s0[i];
            ((float4*)(sm + OFF_D1 + c * SD_STRIDE))[o] = s1[i];
        }
        const float* sb = &gB[hc * 12][0];
        for (int i = tid; i < 12 * 48; i += 512) {
            int c = i / 48, o = i - c * 48;
            sm[OFF_B + c * SB_STRIDE + o] = sb[i];
        }
    }
    __syncthreads();

    // ---- pixel coordinates
    const int row = r0 + (tid >> 6);
    const int w   = tid & 63;
    int b, h;
    if (hc < 4)      { b = row;      h = hc; }
    else if (hc < 8) { b = row / 14; h = hc + 4 * (row - b * 14); }
    else             { b = row;      h = hc + 52; }
    const int wc = (w < 4) ? w : ((w < 60) ? 4 + (w & 3) : 8 + (w & 3));

    // ---- load x[t][c] as packed f32x2 pairs (c pairs are adjacent in gmem)
    typedef unsigned long long u64;
    u64 x2[24];
    const ulonglong2* xp = (const ulonglong2*)x + ((size_t)b * T_IN * HW + h * WW + w);
    #pragma unroll
    for (int t = 0; t < T_IN; t++) {
        ulonglong2 v = xp[t * HW];
        x2[2 * t]     = v.x;   // (c0, c1)
        x2[2 * t + 1] = v.y;   // (c2, c3)
    }

    // ---- trend coefficients (affine-in-t moving average, window 25)
    const u64 C12    = 0x4140000041400000ULL;  // (12, 12)
    const u64 C04    = 0x3D23D70A3D23D70AULL;  // (0.04, 0.04)
    const u64 CN04   = 0xBD23D70ABD23D70AULL;  // (-0.04, -0.04)
    u64 S01 = x2[0], S23 = x2[1];
    #pragma unroll
    for (int t = 1; t < T_IN; t++) {
        ADD2(S01, S01, x2[2 * t]);
        ADD2(S23, S23, x2[2 * t + 1]);
    }
    u64 a01, a23, b01, b23, t0, t1;
    FMA2(t0, x2[0], C12, S01); ADD2(t0, t0, x2[22]); MUL2(a01, t0, C04);
    FMA2(t1, x2[1], C12, S23); ADD2(t1, t1, x2[23]); MUL2(a23, t1, C04);
    MUL2(t0, x2[0], CN04); FMA2(b01, x2[22], C04, t0);
    MUL2(t1, x2[1], CN04); FMA2(b23, x2[23], C04, t1);

    // ---- 48 outputs via packed dot products against per-class smem tables
    const float* wbase = sm + wc * SW_STRIDE;
    const float* dbase0 = sm + OFF_D0 + wc * SD_STRIDE;
    const float* dbase1 = sm + OFF_D1 + wc * SD_STRIDE;
    const float* bbase  = sm + OFF_B  + wc * SB_STRIDE;
    float4* op = (float4*)out + ((size_t)b * T_IN * HW + h * WW + w);

    #pragma unroll
    for (int to = 0; to < 12; to++) {
        float res[4];
        #pragma unroll
        for (int co = 0; co < 4; co++) {
            const int o = to * 4 + co;
            const ulonglong2* wr = (const ulonglong2*)(wbase + o * TC);
            u64 acc = 0;  // (0.0f, 0.0f)
            #pragma unroll
            for (int q = 0; q < 12; q++) {
                ulonglong2 wv = wr[q];
                FMA2(acc, x2[2 * q],     wv.x, acc);
                FMA2(acc, x2[2 * q + 1], wv.y, acc);
            }
            ulonglong2 d0 = *(const ulonglong2*)(dbase0 + o * 4);
            ulonglong2 d1 = *(const ulonglong2*)(dbase1 + o * 4);
            FMA2(acc, a01, d0.x, acc);
            FMA2(acc, a23, d0.y, acc);
            FMA2(acc, b01, d1.x, acc);
            FMA2(acc, b23, d1.y, acc);
            float lo, hi;
            UNPACK2(lo, hi, acc);
            res[co] = bbase[o] + lo + hi;
        }
        op[to * HW] = make_float4(res[0], res[1], res[2], res[3]);
    }
}

// ---------------------------------------------------------------------------
extern "C" void kernel_launch(void* const* d_in, const int* in_sizes, int n_in,
                              void* d_out, int out_size) {
    const float* x   = (const float*)d_in[0];
    const float* w_s = (const float*)d_in[1];
    const float* b_s = (const float*)d_in[2];
    const float* w_t = (const float*)d_in[3];
    const float* b_t = (const float*)d_in[4];
    float* out = (float*)d_out;

    cudaFuncSetAttribute(dlinear_main_kernel,
                         cudaFuncAttributeMaxDynamicSharedMemorySize, SMEM_BYTES);

    dlinear_prep_kernel<<<NCLS, 256>>>(w_s, b_s, w_t, b_t);
    dlinear_main_kernel<<<256, 512, SMEM_BYTES>>>(x, out);
}

// round 3
// speedup vs baseline: 1.4828x; 1.4828x over previous
#include <cuda_runtime.h>

// ---------------------------------------------------------------------------
// DLinear_436: per-pixel 48->48 linear map with (hc,wc) position-class weights.
// Trend (moving avg, window 25 >= 2T) is affine in t and folded ENTIRELY into
// the weight table in prep:  W'[o,t,c] = Ws_eff + D0/25
//                                       + [t==0]*(12*D0 - D1)/25
//                                       + [t==11]*(D0 + D1)/25
// Main kernel: 128 blocks x 512 threads (1 wave).  Block = 16 rows of one hc.
// x staged coalesced->class-sorted smem; weights warp-uniform broadcast LDS;
// packed fma.rn.f32x2; outputs staged back and stored coalesced.
// ---------------------------------------------------------------------------

#define T_IN 12
#define HW   4096
#define NO   48
#define TC   48
#define NCLS 144

#define CLS_STRIDE 2320                  // floats per class (mod 32 == 16 -> 64B quad offset)
#define OFF_SB (12 * CLS_STRIDE)         // 27840
#define OFF_X  (OFF_SB + 576)            // 28416
#define SLOT_F 20                        // floats per pixel slot (16 used + pad)
#define NSLOT  1036                      // 4*225 interior + 8*17 edge
#define SMEM_FLOATS (OFF_X + NSLOT * SLOT_F)   // 49136
#define SMEM_BYTES  (SMEM_FLOATS * 4)          // 196544

__device__ float gWc[NCLS][NO][TC];
__device__ float gBc[NCLS][NO];
__device__ float gD0[NCLS][NO][4];
__device__ float gD1[NCLS][NO][4];

typedef unsigned long long u64;
#define FMA2(d,a,b,c) asm("fma.rn.f32x2 %0, %1, %2, %3;" : "=l"(d) : "l"(a), "l"(b), "l"(c))
#define ADD2(d,a,b)   asm("add.rn.f32x2 %0, %1, %2;"     : "=l"(d) : "l"(a), "l"(b))
#define UNPACK2(lo,hi,v) asm("mov.b64 {%0, %1}, %2;" : "=f"(lo), "=f"(hi) : "l"(v))

__device__ __forceinline__ int class_ilist(int hc, int idx[2]) {
    if (hc < 4)  { idx[0] = hc;                  return 1; }
    if (hc < 8)  { idx[0] = hc - 4; idx[1] = hc; return 2; }
    idx[0] = hc - 4;                             return 1;
}

// ---------------------------------------------------------------------------
// prep1: D0/D1 (sum over t / t-weighted of folded (w_t - w_s)) and folded bias.
// ---------------------------------------------------------------------------
__global__ void dlinear_prep1(const float* __restrict__ w_s, const float* __restrict__ b_s,
                              const float* __restrict__ w_t, const float* __restrict__ b_t) {
    int cls = blockIdx.x;
    int hcc = cls / 12, wcc = cls % 12;
    int il[2], jl[2];
    int ni = class_ilist(hcc, il), nj = class_ilist(wcc, jl);
    int tid = threadIdx.x;

    if (tid < 192) {
        int o = tid >> 2, c = tid & 3;
        float d0 = 0.f, d1 = 0.f;
        for (int t = 0; t < T_IN; t++) {
            const float* ps = w_s + ((o * T_IN + t) * 4 + c) * 64;
            const float* pt = w_t + ((o * T_IN + t) * 4 + c) * 64;
            float d = 0.f;
            for (int a = 0; a < ni; a++)
                for (int e = 0; e < nj; e++) {
                    int off = il[a] * 8 + jl[e];
                    d += pt[off] - ps[off];
                }
            d0 += d;
            d1 += (float)t * d;
        }
        gD0[cls][o][c] = d0;
        gD1[cls][o][c] = d1;
    }
    if (tid < 48) {
        float s = 0.f;
        for (int a = 0; a < ni; a++)
            for (int e = 0; e < nj; e++) {
                int off = tid * 64 + il[a] * 8 + jl[e];
                s += b_s[off] + b_t[off];
            }
        gBc[cls][tid] = s;
    }
}

// ---------------------------------------------------------------------------
// prep2: folded seasonal weights + trend absorption -> gWc.
// ---------------------------------------------------------------------------
__global__ void dlinear_prep2(const float* __restrict__ w_s) {
    int cls = blockIdx.x;
    int hcc = cls / 12, wcc = cls % 12;
    int il[2], jl[2];
    int ni = class_ilist(hcc, il), nj = class_ilist(wcc, jl);

    for (int i = threadIdx.x; i < NO * TC; i += blockDim.x) {
        int o = i / TC, tc = i % TC, t = tc >> 2, c = tc & 3;
        const float* wp = w_s + (o * TC + tc) * 64;
        float s = 0.f;
        for (int a = 0; a < ni; a++)
            for (int e = 0; e < nj; e++)
                s += wp[il[a] * 8 + jl[e]];
        float d0 = gD0[cls][o][c], d1 = gD1[cls][o][c];
        float wv = s + (1.f / 25.f) * d0;
        if (t == 0)  wv += (1.f / 25.f) * (12.f * d0 - d1);
        if (t == 11) wv += (1.f / 25.f) * (d0 + d1);
        gWc[cls][o][tc] = wv;
    }
}

// ---------------------------------------------------------------------------
// Main.  128 blocks x 512 threads.  Block = 16 rows (b,h) of one hc class.
//   bid < 112 : interior hc = 4 + bid/28, rows rho0=(bid%28)*16 of 448
//   bid >= 112: edge e2=bid-112, g=e2>>1, hc = g<4 ? g : g+4, rho0=(e2&1)*16
// Sorted pixel order per block: interior classes c=0..3 (225-slot stride,
// 224 used), then 8 edge classes (17-slot stride, 16 used).
// ---------------------------------------------------------------------------
__global__ __launch_bounds__(512, 1)
void dlinear_main_kernel(const float* __restrict__ x, float* __restrict__ out) {
    extern __shared__ float sm[];
    const int tid = threadIdx.x;
    const int bid = blockIdx.x;

    int hc, rho0;
    if (bid < 112) { int a = bid / 28; hc = 4 + a; rho0 = (bid - a * 28) * 16; }
    else { int e2 = bid - 112; int g = e2 >> 1; hc = (g < 4) ? g : g + 4; rho0 = (e2 & 1) * 16; }

    // ---- weights -> smem (class stride 2320 floats => classes 64B apart mod 128)
    {
        const float4* srcW = (const float4*)&gWc[hc * 12][0][0];
        for (int i = tid; i < 12 * 576; i += 512) {
            int c = i / 576, q = i - c * 576;
            *((float4*)(sm + c * CLS_STRIDE) + q) = srcW[i];
        }
        const float* srcB = &gBc[hc * 12][0];
        for (int i = tid; i < 576; i += 512) sm[OFF_SB + i] = srcB[i];
    }

    // ---- loader-side mapping (row-major pixel m -> gmem idx + sorted slot)
    int gidx[2], slot[2];
    #pragma unroll
    for (int it = 0; it < 2; it++) {
        int m = tid + it * 512;
        int r = m >> 6, w = m & 63;
        int rho = rho0 + r;
        int b, h;
        if (hc < 4)      { b = rho; h = hc; }
        else if (hc < 8) { b = rho / 14; h = (hc - 4) + 4 * (1 + rho - b * 14); }
        else             { b = rho; h = hc + 52; }
        gidx[it] = b * T_IN * HW + h * 64 + w;   // float4 units
        int s;
        if (w >= 4 && w < 60) { int c = w & 3, k = (w - 4) >> 2; s = 225 * c + r * 14 + k; }
        else                  { int e = (w < 4) ? w : 4 + (w - 60); s = 900 + 17 * e + r; }
        slot[it] = s;
    }

    // ---- compute-side mapping: thread tau -> class + 2 adjacent sorted slots
    int wc, cs0;
    if (tid < 448) { int c = tid / 112; int u = tid - c * 112; wc = 4 + c; cs0 = 225 * c + 2 * u; }
    else { int u = tid - 448; int e = u >> 3; int v = u & 7; wc = (e < 4) ? e : 4 + e; cs0 = 900 + 17 * e + 2 * v; }
    const ulonglong2* rx0 = (const ulonglong2*)(sm + OFF_X + cs0 * SLOT_F);
    const ulonglong2* rx1 = (const ulonglong2*)(sm + OFF_X + (cs0 + 1) * SLOT_F);

    u64 x2[2][24];
    const float4* xg = (const float4*)x;

    // ---- stage x in 3 chunks of 4 t (coalesced LDG -> sorted STS -> reg LDS)
    #pragma unroll
    for (int ch = 0; ch < 3; ch++) {
        #pragma unroll
        for (int it = 0; it < 2; it++) {
            float4* dst = (float4*)(sm + OFF_X + slot[it] * SLOT_F);
            #pragma unroll
            for (int tt = 0; tt < 4; tt++)
                dst[tt] = xg[gidx[it] + (ch * 4 + tt) * HW];
        }
        __syncthreads();
        #pragma unroll
        for (int tt = 0; tt < 4; tt++) {
            ulonglong2 v0 = rx0[tt];
            ulonglong2 v1 = rx1[tt];
            x2[0][(ch * 4 + tt) * 2]     = v0.x;
            x2[0][(ch * 4 + tt) * 2 + 1] = v0.y;
            x2[1][(ch * 4 + tt) * 2]     = v1.x;
            x2[1][(ch * 4 + tt) * 2 + 1] = v1.y;
        }
        __syncthreads();
    }

    // ---- 48 outputs: warp-uniform weight broadcast, 2 pixels per thread
    const float* wb = sm + wc * CLS_STRIDE;
    const float* bb = sm + OFF_SB + wc * NO;
    float4* og = (float4*)out;

    #pragma unroll 1
    for (int grp = 0; grp < 6; grp++) {
        #pragma unroll
        for (int sub = 0; sub < 2; sub++) {
            int to = grp * 2 + sub;
            float res0[4], res1[4];
            #pragma unroll
            for (int co = 0; co < 4; co++) {
                int o = to * 4 + co;
                const ulonglong2* wr = (const ulonglong2*)(wb + o * TC);
                u64 a0 = 0, b0 = 0, a1 = 0, b1 = 0;
                #pragma unroll
                for (int q = 0; q < 6; q++) {
                    ulonglong2 w0 = wr[2 * q];
                    ulonglong2 w1 = wr[2 * q + 1];
                    FMA2(a0, x2[0][4 * q],     w0.x, a0);
                    FMA2(b0, x2[0][4 * q + 1], w0.y, b0);
                    FMA2(a0, x2[0][4 * q + 2], w1.x, a0);
                    FMA2(b0, x2[0][4 * q + 3], w1.y, b0);
                    FMA2(a1, x2[1][4 * q],     w0.x, a1);
                    FMA2(b1, x2[1][4 * q + 1], w0.y, b1);
                    FMA2(a1, x2[1][4 * q + 2], w1.x, a1);
                    FMA2(b1, x2[1][4 * q + 3], w1.y, b1);
                }
                float lo, hi;
                ADD2(a0, a0, b0); UNPACK2(lo, hi, a0); res0[co] = bb[o] + lo + hi;
                ADD2(a1, a1, b1); UNPACK2(lo, hi, a1); res1[co] = bb[o] + lo + hi;
            }
            ((float4*)(sm + OFF_X + cs0 * SLOT_F))[sub] =
                make_float4(res0[0], res0[1], res0[2], res0[3]);
            ((float4*)(sm + OFF_X + (cs0 + 1) * SLOT_F))[sub] =
                make_float4(res1[0], res1[1], res1[2], res1[3]);
        }
        __syncthreads();
        #pragma unroll
        for (int it = 0; it < 2; it++) {
            const float4* sp = (const float4*)(sm + OFF_X + slot[it] * SLOT_F);
            #pragma unroll
            for (int sub = 0; sub < 2; sub++)
                og[gidx[it] + (grp * 2 + sub) * HW] = sp[sub];
        }
        if (grp < 5) __syncthreads();
    }
}

// ---------------------------------------------------------------------------
extern "C" void kernel_launch(void* const* d_in, const int* in_sizes, int n_in,
                              void* d_out, int out_size) {
    const float* x   = (const float*)d_in[0];
    const float* w_s = (const float*)d_in[1];
    const float* b_s = (const float*)d_in[2];
    const float* w_t = (const float*)d_in[3];
    const float* b_t = (const float*)d_in[4];
    float* out = (float*)d_out;

    cudaFuncSetAttribute(dlinear_main_kernel,
                         cudaFuncAttributeMaxDynamicSharedMemorySize, SMEM_BYTES);

    dlinear_prep1<<<NCLS, 192>>>(w_s, b_s, w_t, b_t);
    dlinear_prep2<<<NCLS, 256>>>(w_s);
    dlinear_main_kernel<<<128, 512, SMEM_BYTES>>>(x, out);
}

// round 4
// speedup vs baseline: 1.9285x; 1.3006x over previous
#include <cuda_runtime.h>

// ---------------------------------------------------------------------------
// DLinear_436: per-pixel 48->48 linear map with (hc,wc) position-class weights.
// Trend (moving avg, window 25 >= 2T) is affine in t and folded ENTIRELY into
// the weight table:  W'[o,t,c] = Ws_eff + D0/25 + [t==0](12D0-D1)/25
//                                        + [t==11](D0+D1)/25
// Prep is a separable two-stage fold (i axis once, then j axis per class)
// instead of a per-class rescan: ~5us instead of ~25us.
// Main kernel: 128 blocks x 512 threads (1 wave).  Block = 16 rows of one hc.
// x staged coalesced->class-sorted smem; weights warp-uniform broadcast LDS;
// packed fma.rn.f32x2; outputs staged back and stored coalesced.
// ---------------------------------------------------------------------------

#define T_IN 12
#define HW   4096
#define NO   48
#define TC   48
#define NCLS 144

#define CLS_STRIDE 2320                  // floats per class (mod 32 == 16)
#define OFF_SB (12 * CLS_STRIDE)         // 27840
#define OFF_X  (OFF_SB + 576)            // 28416
#define SLOT_F 20                        // floats per pixel slot (16 used + pad)
#define NSLOT  1036                      // 4*225 interior + 8*17 edge
#define SMEM_FLOATS (OFF_X + NSLOT * SLOT_F)   // 49136
#define SMEM_BYTES  (SMEM_FLOATS * 4)          // 196544

// Final per-class tables
__device__ float gWc[NCLS][NO][TC];
__device__ float gBc[NCLS][NO];
// Intermediate separable-fold tables
__device__ float gAs [12][NO][8][TC];    // i-folded w_s      [hc][o][j][tc]
__device__ float gAd [12][NO][8][TC];    // i-folded (w_t-w_s)
__device__ float gD0h[12][NO][8][4];     // sum_t gAd         [hc][o][j][c]
__device__ float gD1h[12][NO][8][4];     // sum_t t*gAd

typedef unsigned long long u64;
#define FMA2(d,a,b,c) asm("fma.rn.f32x2 %0, %1, %2, %3;" : "=l"(d) : "l"(a), "l"(b), "l"(c))
#define ADD2(d,a,b)   asm("add.rn.f32x2 %0, %1, %2;"     : "=l"(d) : "l"(a), "l"(b))
#define UNPACK2(lo,hi,v) asm("mov.b64 {%0, %1}, %2;" : "=f"(lo), "=f"(hi) : "l"(v))

__device__ __forceinline__ int class_ilist(int hc, int idx[2]) {
    if (hc < 4)  { idx[0] = hc;                  return 1; }
    if (hc < 8)  { idx[0] = hc - 4; idx[1] = hc; return 2; }
    idx[0] = hc - 4;                             return 1;
}

// ---------------------------------------------------------------------------
// prepA: fold the i axis for all 12 hc classes at once.
// thread n = ((o*12+t)*4+c)*8 + j,  18432 threads.
// ---------------------------------------------------------------------------
__global__ void dlinear_prepA(const float* __restrict__ w_s,
                              const float* __restrict__ w_t) {
    int n = blockIdx.x * blockDim.x + threadIdx.x;
    if (n >= NO * T_IN * 4 * 8) return;
    int j  = n & 7;
    int tc_row = n >> 3;            // (o*12+t)*4+c
    int t  = (n >> 5) % 12;
    int o  = (n >> 5) / 12;
    int c  = (n >> 3) & 3;
    int tc = t * 4 + c;

    int base = tc_row * 64 + j;
    float v[8], d[8];
    #pragma unroll
    for (int i = 0; i < 8; i++) {
        float a = w_s[base + 8 * i];
        float b = w_t[base + 8 * i];
        v[i] = a;
        d[i] = b - a;
    }
    #pragma unroll
    for (int m = 0; m < 4; m++) {
        gAs[m][o][j][tc]     = v[m];
        gAs[m + 4][o][j][tc] = v[m] + v[m + 4];
        gAs[m + 8][o][j][tc] = v[m + 4];
        gAd[m][o][j][tc]     = d[m];
        gAd[m + 4][o][j][tc] = d[m] + d[m + 4];
        gAd[m + 8][o][j][tc] = d[m + 4];
    }
}

// ---------------------------------------------------------------------------
// prepA2: (a) t-reduce gAd -> gD0h/gD1h (18432 threads)
//         (b) bias fold -> gBc          (6912 threads)
// ---------------------------------------------------------------------------
__global__ void dlinear_prepA2(const float* __restrict__ b_s,
                               const float* __restrict__ b_t) {
    int n = blockIdx.x * blockDim.x + threadIdx.x;
    if (n < 12 * NO * 8 * 4) {
        int c = n & 3, j = (n >> 2) & 7;
        int rest = n >> 5;
        int o = rest % NO, hc = rest / NO;
        float d0 = 0.f, d1 = 0.f;
        #pragma unroll
        for (int t = 0; t < T_IN; t++) {
            float d = gAd[hc][o][j][t * 4 + c];
            d0 += d;
            d1 += (float)t * d;
        }
        gD0h[hc][o][j][c] = d0;
        gD1h[hc][o][j][c] = d1;
        return;
    }
    int m = n - 12 * NO * 8 * 4;
    if (m < NCLS * NO) {
        int o = m % NO, cls = m / NO;
        int hc = cls / 12, wc = cls % 12;
        int il[2], jl[2];
        int ni = class_ilist(hc, il), nj = class_ilist(wc, jl);
        float s = 0.f;
        for (int a = 0; a < ni; a++)
            for (int e = 0; e < nj; e++) {
                int off = o * 64 + il[a] * 8 + jl[e];
                s += b_s[off] + b_t[off];
            }
        gBc[cls][o] = s;
    }
}

// ---------------------------------------------------------------------------
// prepB: fold the j axis per class + absorb trend -> gWc.  331776 threads.
// ---------------------------------------------------------------------------
__global__ void dlinear_prepB() {
    int n = blockIdx.x * blockDim.x + threadIdx.x;
    if (n >= NCLS * NO * TC) return;
    int tc = n % TC;
    int o  = (n / TC) % NO;
    int cls = n / (NO * TC);
    int hc = cls / 12, wc = cls % 12;
    int t = tc >> 2, c = tc & 3;

    int jl[2];
    int nj = class_ilist(wc, jl);

    float s = 0.f, d0 = 0.f, d1 = 0.f;
    for (int e = 0; e < nj; e++) {
        int j = jl[e];
        s  += gAs [hc][o][j][tc];
        d0 += gD0h[hc][o][j][c];
        d1 += gD1h[hc][o][j][c];
    }
    float wv = s + (1.f / 25.f) * d0;
    if (t == 0)  wv += (1.f / 25.f) * (12.f * d0 - d1);
    if (t == 11) wv += (1.f / 25.f) * (d0 + d1);
    gWc[cls][o][tc] = wv;
}

// ---------------------------------------------------------------------------
// Main.  128 blocks x 512 threads.  Block = 16 rows (b,h) of one hc class.
//   bid < 112 : interior hc = 4 + bid/28, rows rho0=(bid%28)*16 of 448
//   bid >= 112: edge e2=bid-112, g=e2>>1, hc = g<4 ? g : g+4, rho0=(e2&1)*16
// ---------------------------------------------------------------------------
__global__ __launch_bounds__(512, 1)
void dlinear_main_kernel(const float* __restrict__ x, float* __restrict__ out) {
    extern __shared__ float sm[];
    const int tid = threadIdx.x;
    const int bid = blockIdx.x;

    int hc, rho0;
    if (bid < 112) { int a = bid / 28; hc = 4 + a; rho0 = (bid - a * 28) * 16; }
    else { int e2 = bid - 112; int g = e2 >> 1; hc = (g < 4) ? g : g + 4; rho0 = (e2 & 1) * 16; }

    // ---- weights -> smem (class stride 2320 floats)
    {
        const float4* srcW = (const float4*)&gWc[hc * 12][0][0];
        for (int i = tid; i < 12 * 576; i += 512) {
            int c = i / 576, q = i - c * 576;
            *((float4*)(sm + c * CLS_STRIDE) + q) = srcW[i];
        }
        const float* srcB = &gBc[hc * 12][0];
        for (int i = tid; i < 576; i += 512) sm[OFF_SB + i] = srcB[i];
    }

    // ---- loader-side mapping (row-major pixel m -> gmem idx + sorted slot)
    int gidx[2], slot[2];
    #pragma unroll
    for (int it = 0; it < 2; it++) {
        int m = tid + it * 512;
        int r = m >> 6, w = m & 63;
        int rho = rho0 + r;
        int b, h;
        if (hc < 4)      { b = rho; h = hc; }
        else if (hc < 8) { b = rho / 14; h = (hc - 4) + 4 * (1 + rho - b * 14); }
        else             { b = rho; h = hc + 52; }
        gidx[it] = b * T_IN * HW + h * 64 + w;   // float4 units
        int s;
        if (w >= 4 && w < 60) { int c = w & 3, k = (w - 4) >> 2; s = 225 * c + r * 14 + k; }
        else                  { int e = (w < 4) ? w : 4 + (w - 60); s = 900 + 17 * e + r; }
        slot[it] = s;
    }

    // ---- compute-side mapping: thread -> class + 2 adjacent sorted slots
    int wc, cs0;
    if (tid < 448) { int c = tid / 112; int u = tid - c * 112; wc = 4 + c; cs0 = 225 * c + 2 * u; }
    else { int u = tid - 448; int e = u >> 3; int v = u & 7; wc = (e < 4) ? e : 4 + e; cs0 = 900 + 17 * e + 2 * v; }
    const ulonglong2* rx0 = (const ulonglong2*)(sm + OFF_X + cs0 * SLOT_F);
    const ulonglong2* rx1 = (const ulonglong2*)(sm + OFF_X + (cs0 + 1) * SLOT_F);

    u64 x2[2][24];
    const float4* xg = (const float4*)x;

    // ---- stage x in 3 chunks of 4 t (coalesced LDG -> sorted STS -> reg LDS)
    #pragma unroll
    for (int ch = 0; ch < 3; ch++) {
        #pragma unroll
        for (int it = 0; it < 2; it++) {
            float4* dst = (float4*)(sm + OFF_X + slot[it] * SLOT_F);
            #pragma unroll
            for (int tt = 0; tt < 4; tt++)
                dst[tt] = xg[gidx[it] + (ch * 4 + tt) * HW];
        }
        __syncthreads();
        #pragma unroll
        for (int tt = 0; tt < 4; tt++) {
            ulonglong2 v0 = rx0[tt];
            ulonglong2 v1 = rx1[tt];
            x2[0][(ch * 4 + tt) * 2]     = v0.x;
            x2[0][(ch * 4 + tt) * 2 + 1] = v0.y;
            x2[1][(ch * 4 + tt) * 2]     = v1.x;
            x2[1][(ch * 4 + tt) * 2 + 1] = v1.y;
        }
        __syncthreads();
    }

    // ---- 48 outputs: warp-uniform weight broadcast, 2 pixels per thread
    const float* wb = sm + wc * CLS_STRIDE;
    const float* bb = sm + OFF_SB + wc * NO;
    float4* og = (float4*)out;

    #pragma unroll 1
    for (int grp = 0; grp < 6; grp++) {
        #pragma unroll
        for (int sub = 0; sub < 2; sub++) {
            int to = grp * 2 + sub;
            float res0[4], res1[4];
            #pragma unroll
            for (int co = 0; co < 4; co++) {
                int o = to * 4 + co;
                const ulonglong2* wr = (const ulonglong2*)(wb + o * TC);
                u64 a0 = 0, b0 = 0, a1 = 0, b1 = 0;
                #pragma unroll
                for (int q = 0; q < 6; q++) {
                    ulonglong2 w0 = wr[2 * q];
                    ulonglong2 w1 = wr[2 * q + 1];
                    FMA2(a0, x2[0][4 * q],     w0.x, a0);
                    FMA2(b0, x2[0][4 * q + 1], w0.y, b0);
                    FMA2(a0, x2[0][4 * q + 2], w1.x, a0);
                    FMA2(b0, x2[0][4 * q + 3], w1.y, b0);
                    FMA2(a1, x2[1][4 * q],     w0.x, a1);
                    FMA2(b1, x2[1][4 * q + 1], w0.y, b1);
                    FMA2(a1, x2[1][4 * q + 2], w1.x, a1);
                    FMA2(b1, x2[1][4 * q + 3], w1.y, b1);
                }
                float lo, hi;
                ADD2(a0, a0, b0); UNPACK2(lo, hi, a0); res0[co] = bb[o] + lo + hi;
                ADD2(a1, a1, b1); UNPACK2(lo, hi, a1); res1[co] = bb[o] + lo + hi;
            }
            ((float4*)(sm + OFF_X + cs0 * SLOT_F))[sub] =
                make_float4(res0[0], res0[1], res0[2], res0[3]);
            ((float4*)(sm + OFF_X + (cs0 + 1) * SLOT_F))[sub] =
                make_float4(res1[0], res1[1], res1[2], res1[3]);
        }
        __syncthreads();
        #pragma unroll
        for (int it = 0; it < 2; it++) {
            const float4* sp = (const float4*)(sm + OFF_X + slot[it] * SLOT_F);
            #pragma unroll
            for (int sub = 0; sub < 2; sub++)
                og[gidx[it] + (grp * 2 + sub) * HW] = sp[sub];
        }
        if (grp < 5) __syncthreads();
    }
}

// ---------------------------------------------------------------------------
extern "C" void kernel_launch(void* const* d_in, const int* in_sizes, int n_in,
                              void* d_out, int out_size) {
    const float* x   = (const float*)d_in[0];
    const float* w_s = (const float*)d_in[1];
    const float* b_s = (const float*)d_in[2];
    const float* w_t = (const float*)d_in[3];
    const float* b_t = (const float*)d_in[4];
    float* out = (float*)d_out;

    cudaFuncSetAttribute(dlinear_main_kernel,
                         cudaFuncAttributeMaxDynamicSharedMemorySize, SMEM_BYTES);

    dlinear_prepA <<<72, 256>>>(w_s, w_t);                  // 18432 threads
    dlinear_prepA2<<<100, 256>>>(b_s, b_t);                 // 18432 + 6912
    dlinear_prepB <<<1296, 256>>>();                        // 331776 threads
    dlinear_main_kernel<<<128, 512, SMEM_BYTES>>>(x, out);
}

// round 5
// speedup vs baseline: 2.1523x; 1.1160x over previous
#include <cuda_runtime.h>

// ---------------------------------------------------------------------------
// DLinear_436: per-pixel 48->48 linear map with (hc,wc) position-class weights.
// Trend (moving avg, window 25 >= 2T) is affine in t and folded ENTIRELY into
// the weight table:  W'[o,t,c] = Ws_eff + D0/25 + [t==0](12D0-D1)/25
//                                        + [t==11](D0+D1)/25
// Prep: separable two-stage fold (i axis once, then j axis per class).
// Main: 128 blocks x 512 threads, block = 16 rows of one hc class.
//   Weights in smem (113KB, warp-uniform broadcast LDS).  Threads read their
//   class-sorted pixels DIRECTLY from gmem (64B-strided lanes; L1 lines are
//   shared across the block's interleaved classes so DRAM traffic stays 1x)
//   and store results directly.  No staging, one __syncthreads total.
// ---------------------------------------------------------------------------

#define T_IN 12
#define HW   4096
#define NO   48
#define TC   48
#define NCLS 144

#define CLS_STRIDE 2320                  // floats per class (16B aligned)
#define OFF_SB (12 * CLS_STRIDE)         // 27840
#define SMEM_FLOATS (OFF_SB + 576)       // 28416
#define SMEM_BYTES  (SMEM_FLOATS * 4)    // 113664

// Final per-class tables
__device__ float gWc[NCLS][NO][TC];
__device__ float gBc[NCLS][NO];
// Intermediate separable-fold tables
__device__ float gAs [12][NO][8][TC];    // i-folded w_s      [hc][o][j][tc]
__device__ float gAd [12][NO][8][TC];    // i-folded (w_t-w_s)
__device__ float gD0h[12][NO][8][4];     // sum_t gAd         [hc][o][j][c]
__device__ float gD1h[12][NO][8][4];     // sum_t t*gAd

typedef unsigned long long u64;
#define FMA2(d,a,b,c) asm("fma.rn.f32x2 %0, %1, %2, %3;" : "=l"(d) : "l"(a), "l"(b), "l"(c))
#define ADD2(d,a,b)   asm("add.rn.f32x2 %0, %1, %2;"     : "=l"(d) : "l"(a), "l"(b))
#define UNPACK2(lo,hi,v) asm("mov.b64 {%0, %1}, %2;" : "=f"(lo), "=f"(hi) : "l"(v))

__device__ __forceinline__ int class_ilist(int hc, int idx[2]) {
    if (hc < 4)  { idx[0] = hc;                  return 1; }
    if (hc < 8)  { idx[0] = hc - 4; idx[1] = hc; return 2; }
    idx[0] = hc - 4;                             return 1;
}

// ---------------------------------------------------------------------------
// prepA: fold the i axis for all 12 hc classes at once.  18432 threads.
// ---------------------------------------------------------------------------
__global__ void dlinear_prepA(const float* __restrict__ w_s,
                              const float* __restrict__ w_t) {
    int n = blockIdx.x * blockDim.x + threadIdx.x;
    if (n >= NO * T_IN * 4 * 8) return;
    int j  = n & 7;
    int tc_row = n >> 3;            // (o*12+t)*4+c
    int t  = (n >> 5) % 12;
    int o  = (n >> 5) / 12;
    int c  = (n >> 3) & 3;
    int tc = t * 4 + c;

    int base = tc_row * 64 + j;
    float v[8], d[8];
    #pragma unroll
    for (int i = 0; i < 8; i++) {
        float a = w_s[base + 8 * i];
        float b = w_t[base + 8 * i];
        v[i] = a;
        d[i] = b - a;
    }
    #pragma unroll
    for (int m = 0; m < 4; m++) {
        gAs[m][o][j][tc]     = v[m];
        gAs[m + 4][o][j][tc] = v[m] + v[m + 4];
        gAs[m + 8][o][j][tc] = v[m + 4];
        gAd[m][o][j][tc]     = d[m];
        gAd[m + 4][o][j][tc] = d[m] + d[m + 4];
        gAd[m + 8][o][j][tc] = d[m + 4];
    }
}

// ---------------------------------------------------------------------------
// prepA2: (a) t-reduce gAd -> gD0h/gD1h  (b) bias fold -> gBc
// ---------------------------------------------------------------------------
__global__ void dlinear_prepA2(const float* __restrict__ b_s,
                               const float* __restrict__ b_t) {
    int n = blockIdx.x * blockDim.x + threadIdx.x;
    if (n < 12 * NO * 8 * 4) {
        int c = n & 3, j = (n >> 2) & 7;
        int rest = n >> 5;
        int o = rest % NO, hc = rest / NO;
        float d0 = 0.f, d1 = 0.f;
        #pragma unroll
        for (int t = 0; t < T_IN; t++) {
            float d = gAd[hc][o][j][t * 4 + c];
            d0 += d;
            d1 += (float)t * d;
        }
        gD0h[hc][o][j][c] = d0;
        gD1h[hc][o][j][c] = d1;
        return;
    }
    int m = n - 12 * NO * 8 * 4;
    if (m < NCLS * NO) {
        int o = m % NO, cls = m / NO;
        int hc = cls / 12, wc = cls % 12;
        int il[2], jl[2];
        int ni = class_ilist(hc, il), nj = class_ilist(wc, jl);
        float s = 0.f;
        for (int a = 0; a < ni; a++)
            for (int e = 0; e < nj; e++) {
                int off = o * 64 + il[a] * 8 + jl[e];
                s += b_s[off] + b_t[off];
            }
        gBc[cls][o] = s;
    }
}

// ---------------------------------------------------------------------------
// prepB: fold the j axis per class + absorb trend -> gWc.  331776 threads.
// ---------------------------------------------------------------------------
__global__ void dlinear_prepB() {
    int n = blockIdx.x * blockDim.x + threadIdx.x;
    if (n >= NCLS * NO * TC) return;
    int tc = n % TC;
    int o  = (n / TC) % NO;
    int cls = n / (NO * TC);
    int hc = cls / 12, wc = cls % 12;
    int t = tc >> 2, c = tc & 3;

    int jl[2];
    int nj = class_ilist(wc, jl);

    float s = 0.f, d0 = 0.f, d1 = 0.f;
    for (int e = 0; e < nj; e++) {
        int j = jl[e];
        s  += gAs [hc][o][j][tc];
        d0 += gD0h[hc][o][j][c];
        d1 += gD1h[hc][o][j][c];
    }
    float wv = s + (1.f / 25.f) * d0;
    if (t == 0)  wv += (1.f / 25.f) * (12.f * d0 - d1);
    if (t == 11) wv += (1.f / 25.f) * (d0 + d1);
    gWc[cls][o][tc] = wv;
}

// ---------------------------------------------------------------------------
// Main.  128 blocks x 512 threads.  Block = 16 rows (b,h) of one hc class.
//   bid < 112 : interior hc = 4 + bid/28, rows rho0=(bid%28)*16 of 448
//   bid >= 112: edge e2=bid-112, g=e2>>1, hc = g<4 ? g : g+4, rho0=(e2&1)*16
// Thread -> one wc class + 2 pixels (rows r and r+8, SAME w).
//   tid < 448 : interior class c=tid/112, u=tid%112: r=u/14, k=u%14,
//               w=4+4k+c  (lanes 64B-strided in gmem)
//   tid >= 448: edge e=(tid-448)/8, v=(tid-448)%8: r=v, w=class column
// ---------------------------------------------------------------------------
__global__ __launch_bounds__(512, 1)
void dlinear_main_kernel(const float* __restrict__ x, float* __restrict__ out) {
    extern __shared__ float sm[];
    const int tid = threadIdx.x;
    const int bid = blockIdx.x;

    int hc, rho0;
    if (bid < 112) { int a = bid / 28; hc = 4 + a; rho0 = (bid - a * 28) * 16; }
    else { int e2 = bid - 112; int g = e2 >> 1; hc = (g < 4) ? g : g + 4; rho0 = (e2 & 1) * 16; }

    // ---- weights + bias -> smem
    {
        const float4* srcW = (const float4*)&gWc[hc * 12][0][0];
        for (int i = tid; i < 12 * 576; i += 512) {
            int c = i / 576, q = i - c * 576;
            *((float4*)(sm + c * CLS_STRIDE) + q) = srcW[i];
        }
        const float* srcB = &gBc[hc * 12][0];
        if (tid < 512) { int i = tid; if (i < 576) sm[OFF_SB + i] = srcB[i]; }
        if (tid < 64) sm[OFF_SB + 512 + tid] = srcB[512 + tid];
    }

    // ---- thread -> class + 2 pixel rows (same w)
    int wc, r0, w;
    if (tid < 448) {
        int c = tid / 112;
        int u = tid - c * 112;
        wc = 4 + c;
        r0 = u / 14;
        int k = u - r0 * 14;
        w = 4 + 4 * k + c;
    } else {
        int u = tid - 448;
        int e = u >> 3;
        int v = u & 7;
        wc = (e < 4) ? e : 4 + e;
        r0 = v;
        w = (wc < 4) ? wc : 52 + wc;   // wc>=8 -> 60 + (wc-8)
    }

    int gidx[2];
    #pragma unroll
    for (int it = 0; it < 2; it++) {
        int rho = rho0 + r0 + it * 8;
        int b, h;
        if (hc < 4)      { b = rho; h = hc; }
        else if (hc < 8) { b = rho / 14; h = (hc - 4) + 4 * (1 + rho - b * 14); }
        else             { b = rho; h = hc + 52; }
        gidx[it] = b * T_IN * HW + h * 64 + w;   // in float4 (16B) units
    }

    __syncthreads();

    // ---- front-batched direct loads of x[t][c] (float4 = (c0..c3) per t)
    u64 x2[2][24];
    const ulonglong2* xg = (const ulonglong2*)x;
    #pragma unroll
    for (int t = 0; t < T_IN; t++) {
        ulonglong2 v0 = xg[gidx[0] + t * HW];
        ulonglong2 v1 = xg[gidx[1] + t * HW];
        x2[0][2 * t] = v0.x;  x2[0][2 * t + 1] = v0.y;
        x2[1][2 * t] = v1.x;  x2[1][2 * t + 1] = v1.y;
    }

    // ---- 48 outputs: warp-uniform weight broadcast, direct STG
    const float* wb = sm + wc * CLS_STRIDE;
    const float4* bb4 = (const float4*)(sm + OFF_SB + wc * NO);
    float4* og = (float4*)out;

    #pragma unroll 1
    for (int to = 0; to < 12; to++) {
        float4 bias = bb4[to];
        const float* bp = (const float*)&bias;
        float res0[4], res1[4];
        #pragma unroll
        for (int co = 0; co < 4; co++) {
            const int o = to * 4 + co;
            const ulonglong2* wr = (const ulonglong2*)(wb + o * TC);
            u64 a0 = 0, b0 = 0, a1 = 0, b1 = 0;
            #pragma unroll
            for (int q = 0; q < 6; q++) {
                ulonglong2 w0 = wr[2 * q];
                ulonglong2 w1 = wr[2 * q + 1];
                FMA2(a0, x2[0][4 * q],     w0.x, a0);
                FMA2(b0, x2[0][4 * q + 1], w0.y, b0);
                FMA2(a0, x2[0][4 * q + 2], w1.x, a0);
                FMA2(b0, x2[0][4 * q + 3], w1.y, b0);
                FMA2(a1, x2[1][4 * q],     w0.x, a1);
                FMA2(b1, x2[1][4 * q + 1], w0.y, b1);
                FMA2(a1, x2[1][4 * q + 2], w1.x, a1);
                FMA2(b1, x2[1][4 * q + 3], w1.y, b1);
            }
            float lo, hi;
            ADD2(a0, a0, b0); UNPACK2(lo, hi, a0); res0[co] = bp[co] + lo + hi;
            ADD2(a1, a1, b1); UNPACK2(lo, hi, a1); res1[co] = bp[co] + lo + hi;
        }
        og[gidx[0] + to * HW] = make_float4(res0[0], res0[1], res0[2], res0[3]);
        og[gidx[1] + to * HW] = make_float4(res1[0], res1[1], res1[2], res1[3]);
    }
}

// ---------------------------------------------------------------------------
extern "C" void kernel_launch(void* const* d_in, const int* in_sizes, int n_in,
                              void* d_out, int out_size) {
    const float* x   = (const float*)d_in[0];
    const float* w_s = (const float*)d_in[1];
    const float* b_s = (const float*)d_in[2];
    const float* w_t = (const float*)d_in[3];
    const float* b_t = (const float*)d_in[4];
    float* out = (float*)d_out;

    cudaFuncSetAttribute(dlinear_main_kernel,
                         cudaFuncAttributeMaxDynamicSharedMemorySize, SMEM_BYTES);

    dlinear_prepA <<<72, 256>>>(w_s, w_t);                  // 18432 threads
    dlinear_prepA2<<<100, 256>>>(b_s, b_t);                 // 18432 + 6912
    dlinear_prepB <<<1296, 256>>>();                        // 331776 threads
    dlinear_main_kernel<<<128, 512, SMEM_BYTES>>>(x, out);
}